// round 1
// baseline (speedup 1.0000x reference)
#include <cuda_runtime.h>
#include <math.h>

#define BB 16
#define LL 128
#define HH 100
#define H2 200
#define PP 20
#define CC 210
#define EPSF 1e-8f

// ---------------- scratch (device globals; no allocations) ----------------
__device__ __align__(16) float g_cos[2][BB][LL][LL];      // fw/bw cosine matrices
__device__ float g_norm[4][BB][LL];                       // plain norms: p_fw,p_bw,h_fw,h_bw
__device__ float g_wnorm[4][4][BB][PP][LL];               // [rowset][mlocal][b][p][i]
__device__ __align__(16) float g_att[8][BB][LL][HH];      // attentive vectors
__device__ int   g_last[2][BB];                           // last_p, last_h

// ---------------- K0: last indices from masks ----------------
__global__ void k0_last(const int* __restrict__ mp, const int* __restrict__ mh)
{
    int b = threadIdx.x;
    if (b < BB) {
        int lp = 0, lh = 0;
        for (int j = 0; j < LL; j++) { lp += mp[b*LL + j]; lh += mh[b*LL + j]; }
        g_last[0][b] = max(lp - 1, 0);
        g_last[1][b] = max(lh - 1, 0);
    }
}

// ---------------- K1: plain norms + weighted norms (8 anchors/block) ----------------
__global__ void __launch_bounds__(128) k1_norms(const float* __restrict__ cp,
                                                const float* __restrict__ ch,
                                                const float* __restrict__ params)
{
    int b = blockIdx.y, i0 = blockIdx.x * 8, tid = threadIdx.x;
    __shared__ float vsq[8][4][HH];
    for (int t = tid; t < 8 * 2 * H2; t += 128) {
        int a = t / (2 * H2);
        int rem = t % (2 * H2);
        float v;
        if (rem < H2) v = cp[((size_t)b*LL + i0 + a)*H2 + rem];
        else          v = ch[((size_t)b*LL + i0 + a)*H2 + rem - H2];
        vsq[a][rem / HH][rem % HH] = v * v;
    }
    __syncthreads();
    if (tid < 32) {
        int a = tid >> 2, r = tid & 3;
        float s = 0.f;
        for (int h = 0; h < HH; h++) s += vsq[a][r][h];
        g_norm[r][b][i0 + a] = sqrtf(s);
    }
    for (int t = tid; t < 4 * 4 * PP; t += 128) {
        int r = t / (4 * PP);
        int rem = t % (4 * PP);
        int ml = rem / PP, p = rem % PP;
        int m = (r & 1) ? (2 * ml + 1) : (2 * ml);   // fw rowsets use even params, bw odd
        const float* w = params + (m * PP + p) * HH;
        float s[8] = {0,0,0,0,0,0,0,0};
        for (int h = 0; h < HH; h++) {
            float wv = w[h]; float w2 = wv * wv;
            #pragma unroll
            for (int a = 0; a < 8; a++) s[a] += w2 * vsq[a][r][h];
        }
        #pragma unroll
        for (int a = 0; a < 8; a++) g_wnorm[r][ml][b][p][i0 + a] = sqrtf(s[a]);
    }
}

// ---------------- K2: cosine matrices (4 anchors/block) ----------------
__global__ void __launch_bounds__(128) k2_cos(const float* __restrict__ cp,
                                              const float* __restrict__ ch)
{
    int b = blockIdx.y, i0 = blockIdx.x * 4, j = threadIdx.x;
    __shared__ __align__(16) float pf[4][HH], pb[4][HH];
    for (int t = j; t < 4 * H2; t += 128) {
        int a = t / H2, rem = t % H2;
        float v = cp[((size_t)b*LL + i0 + a)*H2 + rem];
        if (rem < HH) pf[a][rem] = v; else pb[a][rem - HH] = v;
    }
    __syncthreads();
    const float4* rh = (const float4*)(ch + ((size_t)b*LL + j)*H2);
    float df[4] = {0,0,0,0}, db[4] = {0,0,0,0};
    #pragma unroll 5
    for (int c = 0; c < 25; c++) {
        float4 hf = rh[c];
        float4 hb = rh[25 + c];
        #pragma unroll
        for (int a = 0; a < 4; a++) {
            float4 p4 = *(const float4*)&pf[a][4*c];
            df[a] += p4.x*hf.x + p4.y*hf.y + p4.z*hf.z + p4.w*hf.w;
            float4 q4 = *(const float4*)&pb[a][4*c];
            db[a] += q4.x*hb.x + q4.y*hb.y + q4.z*hb.z + q4.w*hb.w;
        }
    }
    #pragma unroll
    for (int a = 0; a < 4; a++) {
        float nf = g_norm[0][b][i0+a] * g_norm[2][b][j];
        float nb = g_norm[1][b][i0+a] * g_norm[3][b][j];
        g_cos[0][b][i0+a][j] = df[a] / fmaxf(nf, EPSF);   // cosine_pairwise: div_safe(a, n1*n2)
        g_cos[1][b][i0+a][j] = db[a] / fmaxf(nb, EPSF);
    }
}

// ---------------- K3: row-wise (over j) stats + attentive h vectors ----------------
__global__ void __launch_bounds__(128) k3_att_rows(const float* __restrict__ ch,
                                                   float* __restrict__ outp)
{
    int b = blockIdx.y, i0 = blockIdx.x * 4, tid = threadIdx.x;
    __shared__ float cf[4][LL], cb[4][LL];
    __shared__ float st[4][4];   // maxf,sumf,maxb,sumb
    #pragma unroll
    for (int a = 0; a < 4; a++) {
        cf[a][tid] = g_cos[0][b][i0+a][tid];
        cb[a][tid] = g_cos[1][b][i0+a][tid];
    }
    __syncthreads();
    if (tid < 8) {
        int a = tid >> 1, d = tid & 1;
        const float* row = d ? cb[a] : cf[a];
        float mx = -INFINITY, s = 0.f;
        for (int j = 0; j < LL; j++) { mx = fmaxf(mx, row[j]); s += row[j]; }
        st[a][d*2 + 0] = mx;
        st[a][d*2 + 1] = s;
    }
    __syncthreads();
    if (tid < HH) {
        float amf[4], amb[4], axf[4], axb[4];
        #pragma unroll
        for (int a = 0; a < 4; a++) { amf[a] = amb[a] = 0.f; axf[a] = axb[a] = -INFINITY; }
        for (int j = 0; j < LL; j++) {
            float hf = ch[((size_t)b*LL + j)*H2 + tid];
            float hb = ch[((size_t)b*LL + j)*H2 + HH + tid];
            #pragma unroll
            for (int a = 0; a < 4; a++) {
                float vf = cf[a][j] * hf;
                amf[a] += vf; axf[a] = fmaxf(axf[a], vf);
                float vb = cb[a][j] * hb;
                amb[a] += vb; axb[a] = fmaxf(axb[a], vb);
            }
        }
        #pragma unroll
        for (int a = 0; a < 4; a++) {
            int i = i0 + a;
            g_att[0][b][i][tid] = amf[a] / fmaxf(st[a][1], EPSF);  // att_mean_h_fw
            g_att[1][b][i][tid] = amb[a] / fmaxf(st[a][3], EPSF);  // att_mean_h_bw
            g_att[4][b][i][tid] = axf[a];                          // att_max_h_fw
            g_att[5][b][i][tid] = axb[a];                          // att_max_h_bw
        }
    }
    if (tid < 4) {
        float* o = outp + ((size_t)b*LL + i0 + tid)*CC;
        o[0] = st[tid][0];
        o[1] = st[tid][1] * (1.f/LL);
        o[2] = st[tid][2];
        o[3] = st[tid][3] * (1.f/LL);
    }
}

// ---------------- K4: column-wise (over i) stats + attentive p vectors ----------------
__global__ void __launch_bounds__(128) k4_att_cols(const float* __restrict__ cp,
                                                   float* __restrict__ outh)
{
    int b = blockIdx.y, j0 = blockIdx.x * 4, tid = threadIdx.x;
    __shared__ float cf[4][LL], cb[4][LL];
    __shared__ float st[4][4];
    {
        float4 vf = *(const float4*)&g_cos[0][b][tid][j0];
        cf[0][tid] = vf.x; cf[1][tid] = vf.y; cf[2][tid] = vf.z; cf[3][tid] = vf.w;
        float4 vb = *(const float4*)&g_cos[1][b][tid][j0];
        cb[0][tid] = vb.x; cb[1][tid] = vb.y; cb[2][tid] = vb.z; cb[3][tid] = vb.w;
    }
    __syncthreads();
    if (tid < 8) {
        int a = tid >> 1, d = tid & 1;
        const float* col = d ? cb[a] : cf[a];
        float mx = -INFINITY, s = 0.f;
        for (int i = 0; i < LL; i++) { mx = fmaxf(mx, col[i]); s += col[i]; }
        st[a][d*2 + 0] = mx;
        st[a][d*2 + 1] = s;
    }
    __syncthreads();
    if (tid < HH) {
        float amf[4], amb[4], axf[4], axb[4];
        #pragma unroll
        for (int a = 0; a < 4; a++) { amf[a] = amb[a] = 0.f; axf[a] = axb[a] = -INFINITY; }
        for (int i = 0; i < LL; i++) {
            float pf = cp[((size_t)b*LL + i)*H2 + tid];
            float pbv = cp[((size_t)b*LL + i)*H2 + HH + tid];
            #pragma unroll
            for (int a = 0; a < 4; a++) {
                float vf = cf[a][i] * pf;
                amf[a] += vf; axf[a] = fmaxf(axf[a], vf);
                float vb = cb[a][i] * pbv;
                amb[a] += vb; axb[a] = fmaxf(axb[a], vb);
            }
        }
        #pragma unroll
        for (int a = 0; a < 4; a++) {
            int j = j0 + a;
            g_att[2][b][j][tid] = amf[a] / fmaxf(st[a][1], EPSF);  // att_mean_p_fw
            g_att[3][b][j][tid] = amb[a] / fmaxf(st[a][3], EPSF);  // att_mean_p_bw
            g_att[6][b][j][tid] = axf[a];                          // att_max_p_fw
            g_att[7][b][j][tid] = axb[a];                          // att_max_p_bw
        }
    }
    if (tid < 4) {
        float* o = outh + ((size_t)b*LL + j0 + tid)*CC;
        o[0] = st[tid][0];
        o[1] = st[tid][1] * (1.f/LL);
        o[2] = st[tid][2];
        o[3] = st[tid][3] * (1.f/LL);
    }
}

// ---------------- K5: all vector-mpm groups (last / att-mean / att-max) ----------------
__global__ void __launch_bounds__(128) k5_vec(const float* __restrict__ cp,
                                              const float* __restrict__ ch,
                                              const float* __restrict__ params,
                                              float* __restrict__ out)
{
    int b = blockIdx.y, side = blockIdx.z, i0 = blockIdx.x * 4, tid = threadIdx.x;
    __shared__ float v1s[4][2][HH];   // anchor rows fw/bw
    __shared__ float v2f[2][HH];      // fixed v2: [0]=fw-last, [1]=bw-first
    __shared__ float v2a[4][4][HH];   // per-anchor att vectors: mean_fw, mean_bw, max_fw, max_bw
    const float* base1 = side == 0 ? cp : ch;
    const float* other = side == 0 ? ch : cp;
    for (int t = tid; t < 4 * H2; t += 128) {
        int a = t / H2, rem = t % H2;
        v1s[a][rem / HH][rem % HH] = base1[((size_t)b*LL + i0 + a)*H2 + rem];
    }
    int lastIdx = g_last[side == 0 ? 1 : 0][b];
    for (int t = tid; t < H2; t += 128) {
        if (t < HH) v2f[0][t] = other[((size_t)b*LL + lastIdx)*H2 + t];
        else        v2f[1][t - HH] = other[(size_t)b*LL*H2 + t];   // row 0 bw part
    }
    int a0 = side == 0 ? 0 : 2, a4 = side == 0 ? 4 : 6;
    for (int t = tid; t < 4 * 4 * HH; t += 128) {
        int a = t / (4 * HH);
        int g = (t / HH) % 4;
        int h = t % HH;
        int att = (g < 2) ? (a0 + g) : (a4 + g - 2);
        v2a[a][g][h] = g_att[att][b][i0 + a][h];
    }
    __syncthreads();
    if (tid < 120) {
        int g = tid / PP, p = tid % PP;
        const int mtab[6] = {0, 1, 4, 5, 6, 7};
        const int btab[6] = {4, 25, 126, 147, 168, 189};
        int m = mtab[g], dir = g & 1, base = btab[g];
        int rowset = side * 2 + dir;
        const float* w = params + (m * PP + p) * HH;
        for (int a = 0; a < 4; a++) {
            const float* v1 = v1s[a][dir];
            const float* v2 = (g == 0) ? v2f[0] : (g == 1) ? v2f[1] : v2a[a][g - 2];
            float s12 = 0.f, s22 = 0.f;
            for (int h = 0; h < HH; h++) {
                float wv = w[h]; float w2 = wv * wv; float x = v2[h];
                s12 += w2 * v1[h] * x;
                s22 += w2 * x * x;
            }
            float n1 = g_wnorm[rowset][m >> 1][b][p][i0 + a];
            float val = s12 / (fmaxf(n1, EPSF) * fmaxf(sqrtf(s22), EPSF));  // cos_sim semantics
            float* o = out + ((size_t)side*BB*LL + (size_t)b*LL + i0 + a)*CC;
            o[base + 1 + p] = val;
            if (p == 0) {
                float d = 0.f, q = 0.f;
                for (int h = 0; h < HH; h++) { float x = v2[h]; d += v1[h]*x; q += x*x; }
                float pn = g_norm[rowset][b][i0 + a];
                o[base] = d / (fmaxf(pn, EPSF) * fmaxf(sqrtf(q), EPSF));
            }
        }
    }
}

// ---------------- K6: pairwise mpm + max/mean reductions ----------------
// z = side*2 + dir. side0: anchors = p rows, tile = h rows, reduce over j -> mv_p.
//                   side1: anchors = h rows, tile = p rows, reduce over i -> mv_h.
__global__ void __launch_bounds__(128) k6_pairwise(const float* __restrict__ cp,
                                                   const float* __restrict__ ch,
                                                   const float* __restrict__ params,
                                                   float* __restrict__ out)
{
    extern __shared__ float smem[];
    float* tile = smem;                 // 128*100
    float* w2s  = smem + 12800;         // 20*100
    float* anch = w2s + 2000;           // 8*100
    float* anw  = anch + 800;           // 8*20
    float* red  = anw + 160;            // 128*21

    int tid = threadIdx.x;
    int b = blockIdx.y;
    int z = blockIdx.z;
    int side = z >> 1, dir = z & 1;
    int i0 = blockIdx.x * 8;

    const float* abase = side == 0 ? cp : ch;
    const float* tbase = (side == 0 ? ch : cp) + (size_t)b*LL*H2 + dir*HH;
    int m = 2 + dir;
    int rA = side == 0 ? dir : 2 + dir;
    int rT = side == 0 ? 2 + dir : dir;

    for (int t = tid; t < PP * HH; t += 128) {
        float wv = params[m * PP * HH + t];
        w2s[t] = wv * wv;
    }
    for (int t = tid; t < 8 * HH; t += 128) {
        int a = t / HH, h = t % HH;
        anch[a*HH + h] = abase[((size_t)b*LL + i0 + a)*H2 + dir*HH + h];
    }
    for (int t = tid; t < 8 * PP; t += 128) {
        int a = t / PP, p = t % PP;
        anw[a*PP + p] = g_wnorm[rA][1][b][p][i0 + a];
    }
    for (int idx = tid; idx < LL * 25; idx += 128) {
        int j = idx / 25, c = idx % 25;
        *(float4*)(tile + j*HH + 4*c) = *(const float4*)(tbase + (size_t)j*H2 + 4*c);
    }
    __syncthreads();

    const float4* v4 = (const float4*)(tile + tid*HH);
    for (int a = 0; a < 8; a++) {
        float acc[PP];
        #pragma unroll
        for (int p = 0; p < PP; p++) acc[p] = 0.f;
        const float4* a4 = (const float4*)(anch + a*HH);
        #pragma unroll 5
        for (int c = 0; c < 25; c++) {
            float4 v = v4[c];
            float4 av = a4[c];
            float4 pr;
            pr.x = v.x*av.x; pr.y = v.y*av.y; pr.z = v.z*av.z; pr.w = v.w*av.w;
            #pragma unroll
            for (int p = 0; p < PP; p++) {
                float4 w = *(const float4*)(w2s + p*HH + 4*c);
                acc[p] += w.x*pr.x + w.y*pr.y + w.z*pr.z + w.w*pr.w;
            }
        }
        #pragma unroll
        for (int p = 0; p < PP; p++) {
            float nwt = g_wnorm[rT][1][b][p][tid];
            red[tid*(PP+1) + p] = acc[p] / fmaxf(anw[a*PP + p] * nwt, EPSF);
        }
        __syncthreads();
        if (tid < PP) {
            float mx = -INFINITY, s = 0.f;
            for (int t = 0; t < LL; t++) {
                float v = red[t*(PP+1) + tid];
                mx = fmaxf(mx, v); s += v;
            }
            float* o = out + ((size_t)side*BB*LL + (size_t)b*LL + i0 + a)*CC;
            o[46 + dir*40 + tid] = mx;
            o[66 + dir*40 + tid] = s * (1.f/LL);
        }
        __syncthreads();
    }
}

// ---------------- launch ----------------
extern "C" void kernel_launch(void* const* d_in, const int* in_sizes, int n_in,
                              void* d_out, int out_size)
{
    const float* cp     = (const float*)d_in[0];
    const int*   mp     = (const int*)d_in[1];
    const float* ch     = (const float*)d_in[2];
    const int*   mh     = (const int*)d_in[3];
    const float* params = (const float*)d_in[4];
    float* out = (float*)d_out;

    cudaFuncSetAttribute(k6_pairwise, cudaFuncAttributeMaxDynamicSharedMemorySize, 73792);

    k0_last<<<1, 32>>>(mp, mh);
    k1_norms<<<dim3(LL/8, BB), 128>>>(cp, ch, params);
    k2_cos<<<dim3(LL/4, BB), 128>>>(cp, ch);
    k3_att_rows<<<dim3(LL/4, BB), 128>>>(ch, out);
    k4_att_cols<<<dim3(LL/4, BB), 128>>>(cp, out + (size_t)BB*LL*CC);
    k5_vec<<<dim3(LL/4, BB, 2), 128>>>(cp, ch, params, out);
    k6_pairwise<<<dim3(LL/8, BB, 4), 128, 73792>>>(cp, ch, params, out);
}

// round 2
// speedup vs baseline: 1.3703x; 1.3703x over previous
#include <cuda_runtime.h>
#include <math.h>

#define BB 16
#define LL 128
#define HH 100
#define H2 200
#define PP 20
#define CC 210
#define EPSF 1e-8f

typedef unsigned long long u64;

__device__ __forceinline__ u64 mul2(u64 a, u64 b) {
    u64 d; asm("mul.rn.f32x2 %0,%1,%2;" : "=l"(d) : "l"(a), "l"(b)); return d;
}
__device__ __forceinline__ void fma2(u64& d, u64 a, u64 b) {
    asm("fma.rn.f32x2 %0,%1,%2,%0;" : "+l"(d) : "l"(a), "l"(b));
}
__device__ __forceinline__ float2 up2(u64 x) {
    float2 r; asm("mov.b64 {%0,%1}, %2;" : "=f"(r.x), "=f"(r.y) : "l"(x)); return r;
}

// ---------------- scratch (device globals) ----------------
__device__ float g_norm[4][BB][LL];                 // plain norms: p_fw,p_bw,h_fw,h_bw
__device__ float g_wnorm[4][4][BB][PP][LL];         // [rowset][mlocal][b][p][i]
__device__ __align__(16) float g_att[8][BB][LL][HH];
__device__ __align__(16) float g_cosT[2][BB][LL][LL];  // [dir][b][j][i] (column-major cos)
__device__ int   g_last[2][BB];
__device__ __align__(16) float g_hp[2][BB][16][LL][2*PP];  // mv_h partials: [..][j][2p]=max [2p+1]=sum

// ---------------- K0: last indices ----------------
__global__ void k0_last(const int* __restrict__ mp, const int* __restrict__ mh)
{
    int b = threadIdx.x;
    if (b < BB) {
        int lp = 0, lh = 0;
        for (int j = 0; j < LL; j++) { lp += mp[b*LL + j]; lh += mh[b*LL + j]; }
        g_last[0][b] = max(lp - 1, 0);
        g_last[1][b] = max(lh - 1, 0);
    }
}

// ---------------- K1: plain + weighted norms ----------------
__global__ void __launch_bounds__(128) k1_norms(const float* __restrict__ cp,
                                                const float* __restrict__ ch,
                                                const float* __restrict__ params)
{
    int b = blockIdx.y, i0 = blockIdx.x * 8, tid = threadIdx.x;
    __shared__ float vsq[8][4][HH];
    for (int t = tid; t < 8 * 2 * H2; t += 128) {
        int a = t / (2 * H2);
        int rem = t % (2 * H2);
        float v;
        if (rem < H2) v = cp[((size_t)b*LL + i0 + a)*H2 + rem];
        else          v = ch[((size_t)b*LL + i0 + a)*H2 + rem - H2];
        vsq[a][rem / HH][rem % HH] = v * v;
    }
    __syncthreads();
    if (tid < 32) {
        int a = tid >> 2, r = tid & 3;
        float s = 0.f;
        for (int h = 0; h < HH; h++) s += vsq[a][r][h];
        g_norm[r][b][i0 + a] = sqrtf(s);
    }
    for (int t = tid; t < 4 * 4 * PP; t += 128) {
        int r = t / (4 * PP);
        int rem = t % (4 * PP);
        int ml = rem / PP, p = rem % PP;
        int m = (r & 1) ? (2 * ml + 1) : (2 * ml);
        const float* w = params + (m * PP + p) * HH;
        float s[8] = {0,0,0,0,0,0,0,0};
        for (int h = 0; h < HH; h++) {
            float wv = w[h]; float w2 = wv * wv;
            #pragma unroll
            for (int a = 0; a < 8; a++) s[a] += w2 * vsq[a][r][h];
        }
        #pragma unroll
        for (int a = 0; a < 8; a++) g_wnorm[r][ml][b][p][i0 + a] = sqrtf(s[a]);
    }
}

// ---------------- K23: cos rows + row stats + attentive h vectors (16 anchors/block) ----
// smem layout (floats): tile[128][200] @0, pan[16][200] @25600, cosr[2][16][128] @28800,
//                       stat[2][16][2] @32896
__global__ void __launch_bounds__(256) k23_rows(const float* __restrict__ cp,
                                                const float* __restrict__ ch,
                                                float* __restrict__ outp)
{
    extern __shared__ float sm[];
    float* tile = sm;
    float* pan  = sm + 25600;
    float* cosr = sm + 28800;
    float* stat = sm + 32896;

    int b = blockIdx.y, i0 = blockIdx.x * 16, tid = threadIdx.x;

    const float4* src = (const float4*)(ch + (size_t)b*LL*H2);
    float4* dst = (float4*)tile;
    for (int t = tid; t < 128 * 50; t += 256) dst[t] = src[t];
    const float4* psrc = (const float4*)(cp + ((size_t)b*LL + i0)*H2);
    float4* pdst = (float4*)pan;
    for (int t = tid; t < 16 * 50; t += 256) pdst[t] = psrc[t];
    __syncthreads();

    int dir = tid >> 7, j = tid & 127;
    {
        const float4* tr = (const float4*)(tile + j*H2 + dir*HH);
        float nj = g_norm[2 + dir][b][j];
        for (int a = 0; a < 16; a++) {
            const float4* ar = (const float4*)(pan + a*H2 + dir*HH);
            float d = 0.f;
            #pragma unroll 5
            for (int c = 0; c < 25; c++) {
                float4 v = tr[c], w = ar[c];
                d += v.x*w.x + v.y*w.y + v.z*w.z + v.w*w.w;
            }
            float ni = g_norm[dir][b][i0 + a];
            float cv = d / fmaxf(ni * nj, EPSF);
            cosr[(dir*16 + a)*128 + j] = cv;
            g_cosT[dir][b][j][i0 + a] = cv;
        }
    }
    __syncthreads();

    int w = tid >> 5, lane = tid & 31;
    for (int task = w; task < 32; task += 8) {
        int d = task >> 4, a = task & 15;
        float mx = -INFINITY, s = 0.f;
        for (int jj = lane; jj < 128; jj += 32) {
            float v = cosr[(d*16 + a)*128 + jj];
            mx = fmaxf(mx, v); s += v;
        }
        #pragma unroll
        for (int o = 16; o; o >>= 1) {
            mx = fmaxf(mx, __shfl_xor_sync(0xffffffffu, mx, o));
            s += __shfl_xor_sync(0xffffffffu, s, o);
        }
        if (lane == 0) { stat[(d*16 + a)*2] = mx; stat[(d*16 + a)*2 + 1] = s; }
    }
    __syncthreads();

    if (tid < 16) {
        float* o = outp + ((size_t)b*LL + i0 + tid)*CC;
        o[0] = stat[tid*2];          o[1] = stat[tid*2 + 1] * (1.f/LL);
        o[2] = stat[(16+tid)*2];     o[3] = stat[(16+tid)*2 + 1] * (1.f/LL);
    }

    if (tid < 200) {
        int d = tid >= 100;
        float inv[16], smv[16], mxv[16];
        #pragma unroll
        for (int a = 0; a < 16; a++) {
            inv[a] = 1.f / fmaxf(stat[(d*16 + a)*2 + 1], EPSF);
            smv[a] = 0.f; mxv[a] = -INFINITY;
        }
        for (int jj = 0; jj < 128; jj++) {
            float hv = tile[jj*H2 + tid];
            #pragma unroll
            for (int a = 0; a < 16; a++) {
                float v = cosr[(d*16 + a)*128 + jj] * hv;
                smv[a] += v; mxv[a] = fmaxf(mxv[a], v);
            }
        }
        int h = d ? tid - 100 : tid;
        for (int a = 0; a < 16; a++) {
            g_att[d ? 1 : 0][b][i0 + a][h] = smv[a] * inv[a];
            g_att[d ? 5 : 4][b][i0 + a][h] = mxv[a];
        }
    }
}

// ---------------- K4: col stats + attentive p vectors (16 j-anchors/block) ----
// smem (floats): tile[128][200] @0, cosc[2][16][128] @25600, stat @29696
__global__ void __launch_bounds__(256) k4_cols(const float* __restrict__ cp,
                                               float* __restrict__ outh)
{
    extern __shared__ float sm[];
    float* tile = sm;
    float* cosc = sm + 25600;
    float* stat = sm + 29696;

    int b = blockIdx.y, j0 = blockIdx.x * 16, tid = threadIdx.x;

    const float4* src = (const float4*)(cp + (size_t)b*LL*H2);
    float4* dst = (float4*)tile;
    for (int t = tid; t < 128 * 50; t += 256) dst[t] = src[t];
    for (int t = tid; t < 2 * 16 * 128; t += 256) {
        int d = t >> 11, a = (t >> 7) & 15, i = t & 127;
        cosc[t] = g_cosT[d][b][j0 + a][i];
    }
    __syncthreads();

    int w = tid >> 5, lane = tid & 31;
    for (int task = w; task < 32; task += 8) {
        int idx = task * 128;
        float mx = -INFINITY, s = 0.f;
        for (int ii = lane; ii < 128; ii += 32) {
            float v = cosc[idx + ii];
            mx = fmaxf(mx, v); s += v;
        }
        #pragma unroll
        for (int o = 16; o; o >>= 1) {
            mx = fmaxf(mx, __shfl_xor_sync(0xffffffffu, mx, o));
            s += __shfl_xor_sync(0xffffffffu, s, o);
        }
        if (lane == 0) { stat[task*2] = mx; stat[task*2 + 1] = s; }
    }
    __syncthreads();

    if (tid < 16) {
        float* o = outh + ((size_t)b*LL + j0 + tid)*CC;
        o[0] = stat[tid*2];          o[1] = stat[tid*2 + 1] * (1.f/LL);
        o[2] = stat[(16+tid)*2];     o[3] = stat[(16+tid)*2 + 1] * (1.f/LL);
    }

    if (tid < 200) {
        int d = tid >= 100;
        float inv[16], smv[16], mxv[16];
        #pragma unroll
        for (int a = 0; a < 16; a++) {
            inv[a] = 1.f / fmaxf(stat[(d*16 + a)*2 + 1], EPSF);
            smv[a] = 0.f; mxv[a] = -INFINITY;
        }
        for (int ii = 0; ii < 128; ii++) {
            float pv = tile[ii*H2 + tid];
            #pragma unroll
            for (int a = 0; a < 16; a++) {
                float v = cosc[(d*16 + a)*128 + ii] * pv;
                smv[a] += v; mxv[a] = fmaxf(mxv[a], v);
            }
        }
        int h = d ? tid - 100 : tid;
        for (int a = 0; a < 16; a++) {
            g_att[d ? 3 : 2][b][j0 + a][h] = smv[a] * inv[a];
            g_att[d ? 7 : 6][b][j0 + a][h] = mxv[a];
        }
    }
}

// ---------------- K5: vector-mpm groups (unchanged) ----------------
__global__ void __launch_bounds__(128) k5_vec(const float* __restrict__ cp,
                                              const float* __restrict__ ch,
                                              const float* __restrict__ params,
                                              float* __restrict__ out)
{
    int b = blockIdx.y, side = blockIdx.z, i0 = blockIdx.x * 4, tid = threadIdx.x;
    __shared__ float v1s[4][2][HH];
    __shared__ float v2f[2][HH];
    __shared__ float v2a[4][4][HH];
    const float* base1 = side == 0 ? cp : ch;
    const float* other = side == 0 ? ch : cp;
    for (int t = tid; t < 4 * H2; t += 128) {
        int a = t / H2, rem = t % H2;
        v1s[a][rem / HH][rem % HH] = base1[((size_t)b*LL + i0 + a)*H2 + rem];
    }
    int lastIdx = g_last[side == 0 ? 1 : 0][b];
    for (int t = tid; t < H2; t += 128) {
        if (t < HH) v2f[0][t] = other[((size_t)b*LL + lastIdx)*H2 + t];
        else        v2f[1][t - HH] = other[(size_t)b*LL*H2 + t];
    }
    int a0 = side == 0 ? 0 : 2, a4 = side == 0 ? 4 : 6;
    for (int t = tid; t < 4 * 4 * HH; t += 128) {
        int a = t / (4 * HH);
        int g = (t / HH) % 4;
        int h = t % HH;
        int att = (g < 2) ? (a0 + g) : (a4 + g - 2);
        v2a[a][g][h] = g_att[att][b][i0 + a][h];
    }
    __syncthreads();
    if (tid < 120) {
        int g = tid / PP, p = tid % PP;
        const int mtab[6] = {0, 1, 4, 5, 6, 7};
        const int btab[6] = {4, 25, 126, 147, 168, 189};
        int m = mtab[g], dir = g & 1, base = btab[g];
        int rowset = side * 2 + dir;
        const float* w = params + (m * PP + p) * HH;
        for (int a = 0; a < 4; a++) {
            const float* v1 = v1s[a][dir];
            const float* v2 = (g == 0) ? v2f[0] : (g == 1) ? v2f[1] : v2a[a][g - 2];
            float s12 = 0.f, s22 = 0.f;
            for (int h = 0; h < HH; h++) {
                float wv = w[h]; float w2 = wv * wv; float x = v2[h];
                s12 += w2 * v1[h] * x;
                s22 += w2 * x * x;
            }
            float n1 = g_wnorm[rowset][m >> 1][b][p][i0 + a];
            float val = s12 / (fmaxf(n1, EPSF) * fmaxf(sqrtf(s22), EPSF));
            float* o = out + ((size_t)side*BB*LL + (size_t)b*LL + i0 + a)*CC;
            o[base + 1 + p] = val;
            if (p == 0) {
                float d = 0.f, q = 0.f;
                for (int h = 0; h < HH; h++) { float x = v2[h]; d += v1[h]*x; q += x*x; }
                float pn = g_norm[rowset][b][i0 + a];
                o[base] = d / (fmaxf(pn, EPSF) * fmaxf(sqrtf(q), EPSF));
            }
        }
    }
}

// ---------------- K6: fused pairwise mpm (computes m once, both reductions) -----
// grid (16 i-chunks, 16 b, 2 dirs). block 128 (thread = j).
// smem (floats): tile[128][100]@0, w2[20][100]@12800, anch[8][100]@14800,
//   invA[8][20]@15600, invT[128][21]@15760, red[128][21]@18448,
//   hm[128][21]@21136, hs[128][21]@23824, part[20][4][2]@26512  -> 26672 floats
__global__ void __launch_bounds__(128) k6_pairwise(const float* __restrict__ cp,
                                                   const float* __restrict__ ch,
                                                   const float* __restrict__ params,
                                                   float* __restrict__ outp)
{
    extern __shared__ float sm[];
    float* tile = sm;
    float* w2s  = sm + 12800;
    float* anch = sm + 14800;
    float* invA = sm + 15600;
    float* invT = sm + 15760;
    float* red  = sm + 18448;
    float* hm   = sm + 21136;
    float* hs   = sm + 23824;
    float* part = sm + 26512;

    int tid = threadIdx.x;
    int b = blockIdx.y;
    int dir = blockIdx.z;
    int ib = blockIdx.x;
    int i0 = ib * 8;
    int m = 2 + dir;

    // stage
    for (int t = tid; t < PP * HH; t += 128) {
        float wv = params[m * PP * HH + t];
        w2s[t] = wv * wv;
    }
    {
        const float* abase = cp + ((size_t)b*LL + i0)*H2 + dir*HH;
        for (int t = tid; t < 8 * 25; t += 128) {
            int a = t / 25, c = t % 25;
            *(float4*)(anch + a*HH + 4*c) = *(const float4*)(abase + (size_t)a*H2 + 4*c);
        }
    }
    {
        const float* tbase = ch + (size_t)b*LL*H2 + dir*HH;
        for (int t = tid; t < 128 * 25; t += 128) {
            int j = t / 25, c = t % 25;
            *(float4*)(tile + j*HH + 4*c) = *(const float4*)(tbase + (size_t)j*H2 + 4*c);
        }
    }
    for (int t = tid; t < 8 * PP; t += 128) {
        int a = t / PP, p = t % PP;
        invA[a*PP + p] = 1.f / fmaxf(g_wnorm[dir][1][b][p][i0 + a], EPSF);
    }
    #pragma unroll
    for (int p = 0; p < PP; p++) {
        invT[tid*(PP+1) + p] = 1.f / fmaxf(g_wnorm[2 + dir][1][b][p][tid], EPSF);
        hm[tid*(PP+1) + p] = -INFINITY;
        hs[tid*(PP+1) + p] = 0.f;
    }
    __syncthreads();

    const ulonglong2* vt = (const ulonglong2*)(tile + tid*HH);
    for (int a = 0; a < 8; a++) {
        const ulonglong2* at = (const ulonglong2*)(anch + a*HH);
        u64 accA[PP], accB[PP];
        #pragma unroll
        for (int p = 0; p < PP; p++) { accA[p] = 0ull; accB[p] = 0ull; }
        #pragma unroll 5
        for (int c = 0; c < 25; c++) {
            ulonglong2 v = vt[c];
            ulonglong2 aa = at[c];
            u64 pr0 = mul2(v.x, aa.x);
            u64 pr1 = mul2(v.y, aa.y);
            #pragma unroll
            for (int p = 0; p < PP; p++) {
                ulonglong2 w = *((const ulonglong2*)(w2s + p*HH) + c);
                fma2(accA[p], w.x, pr0);
                fma2(accB[p], w.y, pr1);
            }
        }
        #pragma unroll
        for (int p = 0; p < PP; p++) {
            float2 x = up2(accA[p]);
            float2 y = up2(accB[p]);
            float s = (x.x + x.y) + (y.x + y.y);
            float v = s * invA[a*PP + p] * invT[tid*(PP+1) + p];
            red[tid*(PP+1) + p] = v;
            hm[tid*(PP+1) + p] = fmaxf(hm[tid*(PP+1) + p], v);
            hs[tid*(PP+1) + p] += v;
        }
        __syncthreads();
        if (tid < 80) {
            int p = tid >> 2, q = tid & 3;
            float mx = -INFINITY, s = 0.f;
            for (int jj = q*32; jj < q*32 + 32; jj++) {
                float v = red[jj*(PP+1) + p];
                mx = fmaxf(mx, v); s += v;
            }
            part[(p*4 + q)*2] = mx; part[(p*4 + q)*2 + 1] = s;
        }
        __syncthreads();
        if (tid < PP) {
            float mx = -INFINITY, s = 0.f;
            #pragma unroll
            for (int q = 0; q < 4; q++) {
                mx = fmaxf(mx, part[(tid*4 + q)*2]);
                s += part[(tid*4 + q)*2 + 1];
            }
            float* o = outp + ((size_t)b*LL + i0 + a)*CC;
            o[46 + dir*40 + tid] = mx;
            o[66 + dir*40 + tid] = s * (1.f/LL);
        }
        __syncthreads();
    }

    // write mv_h partials for this i-chunk
    float* gp = &g_hp[dir][b][ib][tid][0];
    #pragma unroll
    for (int p = 0; p < PP; p++) {
        gp[2*p]     = hm[tid*(PP+1) + p];
        gp[2*p + 1] = hs[tid*(PP+1) + p];
    }
}

// ---------------- K7: reduce mv_h partials over i-chunks ----------------
__global__ void __launch_bounds__(128) k7_reduce(float* __restrict__ out)
{
    int b = blockIdx.x, dir = blockIdx.y, j = threadIdx.x;
    float* o = out + (size_t)BB*LL*CC + ((size_t)b*LL + j)*CC;
    for (int p = 0; p < PP; p++) {
        float mx = -INFINITY, s = 0.f;
        #pragma unroll
        for (int ib = 0; ib < 16; ib++) {
            float2 v = *(const float2*)&g_hp[dir][b][ib][j][2*p];
            mx = fmaxf(mx, v.x); s += v.y;
        }
        o[46 + dir*40 + p] = mx;
        o[66 + dir*40 + p] = s * (1.f/LL);
    }
}

// ---------------- launch ----------------
extern "C" void kernel_launch(void* const* d_in, const int* in_sizes, int n_in,
                              void* d_out, int out_size)
{
    const float* cp     = (const float*)d_in[0];
    const int*   mp     = (const int*)d_in[1];
    const float* ch     = (const float*)d_in[2];
    const int*   mh     = (const int*)d_in[3];
    const float* params = (const float*)d_in[4];
    float* out = (float*)d_out;
    float* out_h = out + (size_t)BB*LL*CC;

    static int attr_done = 0;
    if (!attr_done) {
        cudaFuncSetAttribute(k23_rows,    cudaFuncAttributeMaxDynamicSharedMemorySize, 131840);
        cudaFuncSetAttribute(k4_cols,     cudaFuncAttributeMaxDynamicSharedMemorySize, 119040);
        cudaFuncSetAttribute(k6_pairwise, cudaFuncAttributeMaxDynamicSharedMemorySize, 106688);
        attr_done = 1;
    }

    k0_last<<<1, 32>>>(mp, mh);
    k1_norms<<<dim3(LL/8, BB), 128>>>(cp, ch, params);
    k23_rows<<<dim3(LL/16, BB), 256, 131840>>>(cp, ch, out);
    k4_cols<<<dim3(LL/16, BB), 256, 119040>>>(cp, out_h);
    k5_vec<<<dim3(LL/4, BB, 2), 128>>>(cp, ch, params, out);
    k6_pairwise<<<dim3(LL/8, BB, 2), 128, 106688>>>(cp, ch, params, out);
    k7_reduce<<<dim3(BB, 2), 128>>>(out);
}

// round 3
// speedup vs baseline: 2.0194x; 1.4737x over previous
#include <cuda_runtime.h>
#include <math.h>

#define BB 16
#define LL 128
#define HH 100
#define H2 200
#define PP 20
#define CC 210
#define EPSF 1e-8f

typedef unsigned long long u64;

__device__ __forceinline__ u64 mul2(u64 a, u64 b) {
    u64 d; asm("mul.rn.f32x2 %0,%1,%2;" : "=l"(d) : "l"(a), "l"(b)); return d;
}
__device__ __forceinline__ void fma2(u64& d, u64 a, u64 b) {
    asm("fma.rn.f32x2 %0,%1,%2,%0;" : "+l"(d) : "l"(a), "l"(b));
}
__device__ __forceinline__ float2 up2(u64 x) {
    float2 r; asm("mov.b64 {%0,%1}, %2;" : "=f"(r.x), "=f"(r.y) : "l"(x)); return r;
}

// ---------------- scratch ----------------
__device__ float g_norm[4][BB][LL];
__device__ float g_wnorm[4][4][BB][PP][LL];
__device__ __align__(16) float g_att[8][BB][LL][HH];
__device__ __align__(16) float g_cos[2][BB][LL][LL];   // [dir][b][i][j] row-major
__device__ int   g_last[2][BB];
__device__ __align__(16) float g_hp[2][BB][16][LL][2*PP];

// ---------------- K0 ----------------
__global__ void k0_last(const int* __restrict__ mp, const int* __restrict__ mh)
{
    int b = threadIdx.x;
    if (b < BB) {
        int lp = 0, lh = 0;
        for (int j = 0; j < LL; j++) { lp += mp[b*LL + j]; lh += mh[b*LL + j]; }
        g_last[0][b] = max(lp - 1, 0);
        g_last[1][b] = max(lh - 1, 0);
    }
}

// ---------------- K1: norms ----------------
__global__ void __launch_bounds__(128) k1_norms(const float* __restrict__ cp,
                                                const float* __restrict__ ch,
                                                const float* __restrict__ params)
{
    int b = blockIdx.y, i0 = blockIdx.x * 8, tid = threadIdx.x;
    __shared__ float vsq[8][4][HH];
    for (int t = tid; t < 8 * 2 * H2; t += 128) {
        int a = t / (2 * H2);
        int rem = t % (2 * H2);
        float v;
        if (rem < H2) v = cp[((size_t)b*LL + i0 + a)*H2 + rem];
        else          v = ch[((size_t)b*LL + i0 + a)*H2 + rem - H2];
        vsq[a][rem / HH][rem % HH] = v * v;
    }
    __syncthreads();
    if (tid < 32) {
        int a = tid >> 2, r = tid & 3;
        float s = 0.f;
        for (int h = 0; h < HH; h++) s += vsq[a][r][h];
        g_norm[r][b][i0 + a] = sqrtf(s);
    }
    for (int t = tid; t < 4 * 4 * PP; t += 128) {
        int r = t / (4 * PP);
        int rem = t % (4 * PP);
        int ml = rem / PP, p = rem % PP;
        int m = (r & 1) ? (2 * ml + 1) : (2 * ml);
        const float* w = params + (m * PP + p) * HH;
        float s[8] = {0,0,0,0,0,0,0,0};
        for (int h = 0; h < HH; h++) {
            float wv = w[h]; float w2 = wv * wv;
            #pragma unroll
            for (int a = 0; a < 8; a++) s[a] += w2 * vsq[a][r][h];
        }
        #pragma unroll
        for (int a = 0; a < 8; a++) g_wnorm[r][ml][b][p][i0 + a] = sqrtf(s[a]);
    }
}

// ---------------- K23: cos + row stats + attentive h vectors ----------------
// smem: tile[128][200]@0, pan[16][200]@25600, cosr[2][16][128]@28800, stat[2][16][2]@32896
__global__ void __launch_bounds__(256) k23_rows(const float* __restrict__ cp,
                                                const float* __restrict__ ch,
                                                float* __restrict__ outp)
{
    extern __shared__ float sm[];
    float* tile = sm;
    float* pan  = sm + 25600;
    float* cosr = sm + 28800;
    float* stat = sm + 32896;

    int b = blockIdx.y, i0 = blockIdx.x * 16, tid = threadIdx.x;

    const float4* src = (const float4*)(ch + (size_t)b*LL*H2);
    float4* dst = (float4*)tile;
    for (int t = tid; t < 128 * 50; t += 256) dst[t] = src[t];
    const float4* psrc = (const float4*)(cp + ((size_t)b*LL + i0)*H2);
    float4* pdst = (float4*)pan;
    for (int t = tid; t < 16 * 50; t += 256) pdst[t] = psrc[t];
    __syncthreads();

    int dir = tid >> 7, j = tid & 127;
    {
        const float4* tr = (const float4*)(tile + j*H2 + dir*HH);
        float nj = g_norm[2 + dir][b][j];
        float dacc[16];
        #pragma unroll
        for (int a = 0; a < 16; a++) dacc[a] = 0.f;
        const float4* pb = (const float4*)(pan + dir*HH);
        #pragma unroll 5
        for (int c = 0; c < 25; c++) {
            float4 v = tr[c];
            #pragma unroll
            for (int a = 0; a < 16; a++) {
                float4 w = pb[a*50 + c];
                dacc[a] += v.x*w.x + v.y*w.y + v.z*w.z + v.w*w.w;
            }
        }
        #pragma unroll
        for (int a = 0; a < 16; a++) {
            float ni = g_norm[dir][b][i0 + a];
            float cv = dacc[a] / fmaxf(ni * nj, EPSF);
            cosr[(dir*16 + a)*128 + j] = cv;
            g_cos[dir][b][i0 + a][j] = cv;     // coalesced
        }
    }
    __syncthreads();

    int w = tid >> 5, lane = tid & 31;
    for (int task = w; task < 32; task += 8) {
        int d = task >> 4, a = task & 15;
        float mx = -INFINITY, s = 0.f;
        for (int jj = lane; jj < 128; jj += 32) {
            float v = cosr[(d*16 + a)*128 + jj];
            mx = fmaxf(mx, v); s += v;
        }
        #pragma unroll
        for (int o = 16; o; o >>= 1) {
            mx = fmaxf(mx, __shfl_xor_sync(0xffffffffu, mx, o));
            s += __shfl_xor_sync(0xffffffffu, s, o);
        }
        if (lane == 0) { stat[(d*16 + a)*2] = mx; stat[(d*16 + a)*2 + 1] = s; }
    }
    __syncthreads();

    if (tid < 16) {
        float* o = outp + ((size_t)b*LL + i0 + tid)*CC;
        o[0] = stat[tid*2];          o[1] = stat[tid*2 + 1] * (1.f/LL);
        o[2] = stat[(16+tid)*2];     o[3] = stat[(16+tid)*2 + 1] * (1.f/LL);
    }

    if (tid < 200) {
        int d = tid >= 100;
        float inv[16], smv[16], mxv[16];
        #pragma unroll
        for (int a = 0; a < 16; a++) {
            inv[a] = 1.f / fmaxf(stat[(d*16 + a)*2 + 1], EPSF);
            smv[a] = 0.f; mxv[a] = -INFINITY;
        }
        const float* crow = cosr + d*16*128;
        for (int jj = 0; jj < 128; jj += 2) {
            float hv0 = tile[jj*H2 + tid];
            float hv1 = tile[(jj+1)*H2 + tid];
            #pragma unroll
            for (int a = 0; a < 16; a++) {
                float2 c2 = *(const float2*)&crow[a*128 + jj];
                float v0 = c2.x * hv0, v1 = c2.y * hv1;
                smv[a] += v0; smv[a] += v1;
                mxv[a] = fmaxf(mxv[a], fmaxf(v0, v1));
            }
        }
        int h = d ? tid - 100 : tid;
        for (int a = 0; a < 16; a++) {
            g_att[d ? 1 : 0][b][i0 + a][h] = smv[a] * inv[a];
            g_att[d ? 5 : 4][b][i0 + a][h] = mxv[a];
        }
    }
}

// ---------------- K4: col stats + attentive p vectors ----------------
// smem: tile[128][200]@0, cosc[2][16][128]@25600, stat@29696
__global__ void __launch_bounds__(256) k4_cols(const float* __restrict__ cp,
                                               float* __restrict__ outh)
{
    extern __shared__ float sm[];
    float* tile = sm;
    float* cosc = sm + 25600;
    float* stat = sm + 29696;

    int b = blockIdx.y, j0 = blockIdx.x * 16, tid = threadIdx.x;

    const float4* src = (const float4*)(cp + (size_t)b*LL*H2);
    float4* dst = (float4*)tile;
    for (int t = tid; t < 128 * 50; t += 256) dst[t] = src[t];
    // transpose-load cos: row-chunk reads, scatter into [d][a][i]
    for (int t = tid; t < 2 * 128 * 4; t += 256) {
        int d = t >> 9, rem = t & 511, i = rem >> 2, q = rem & 3;
        float4 v = *(const float4*)&g_cos[d][b][i][j0 + q*4];
        cosc[(d*16 + q*4 + 0)*128 + i] = v.x;
        cosc[(d*16 + q*4 + 1)*128 + i] = v.y;
        cosc[(d*16 + q*4 + 2)*128 + i] = v.z;
        cosc[(d*16 + q*4 + 3)*128 + i] = v.w;
    }
    __syncthreads();

    int w = tid >> 5, lane = tid & 31;
    for (int task = w; task < 32; task += 8) {
        int idx = task * 128;
        float mx = -INFINITY, s = 0.f;
        for (int ii = lane; ii < 128; ii += 32) {
            float v = cosc[idx + ii];
            mx = fmaxf(mx, v); s += v;
        }
        #pragma unroll
        for (int o = 16; o; o >>= 1) {
            mx = fmaxf(mx, __shfl_xor_sync(0xffffffffu, mx, o));
            s += __shfl_xor_sync(0xffffffffu, s, o);
        }
        if (lane == 0) { stat[task*2] = mx; stat[task*2 + 1] = s; }
    }
    __syncthreads();

    if (tid < 16) {
        float* o = outh + ((size_t)b*LL + j0 + tid)*CC;
        o[0] = stat[tid*2];          o[1] = stat[tid*2 + 1] * (1.f/LL);
        o[2] = stat[(16+tid)*2];     o[3] = stat[(16+tid)*2 + 1] * (1.f/LL);
    }

    if (tid < 200) {
        int d = tid >= 100;
        float inv[16], smv[16], mxv[16];
        #pragma unroll
        for (int a = 0; a < 16; a++) {
            inv[a] = 1.f / fmaxf(stat[(d*16 + a)*2 + 1], EPSF);
            smv[a] = 0.f; mxv[a] = -INFINITY;
        }
        const float* crow = cosc + d*16*128;
        for (int ii = 0; ii < 128; ii += 2) {
            float pv0 = tile[ii*H2 + tid];
            float pv1 = tile[(ii+1)*H2 + tid];
            #pragma unroll
            for (int a = 0; a < 16; a++) {
                float2 c2 = *(const float2*)&crow[a*128 + ii];
                float v0 = c2.x * pv0, v1 = c2.y * pv1;
                smv[a] += v0; smv[a] += v1;
                mxv[a] = fmaxf(mxv[a], fmaxf(v0, v1));
            }
        }
        int h = d ? tid - 100 : tid;
        for (int a = 0; a < 16; a++) {
            g_att[d ? 3 : 2][b][j0 + a][h] = smv[a] * inv[a];
            g_att[d ? 7 : 6][b][j0 + a][h] = mxv[a];
        }
    }
}

// ---------------- K5: vector-mpm groups ----------------
__global__ void __launch_bounds__(128) k5_vec(const float* __restrict__ cp,
                                              const float* __restrict__ ch,
                                              const float* __restrict__ params,
                                              float* __restrict__ out)
{
    int b = blockIdx.y, side = blockIdx.z, i0 = blockIdx.x * 4, tid = threadIdx.x;
    __shared__ __align__(16) float v1s[4][2][HH];
    __shared__ __align__(16) float v2f[2][HH];
    __shared__ __align__(16) float v2a[4][4][HH];
    const float* base1 = side == 0 ? cp : ch;
    const float* other = side == 0 ? ch : cp;
    for (int t = tid; t < 4 * H2; t += 128) {
        int a = t / H2, rem = t % H2;
        v1s[a][rem / HH][rem % HH] = base1[((size_t)b*LL + i0 + a)*H2 + rem];
    }
    int lastIdx = g_last[side == 0 ? 1 : 0][b];
    for (int t = tid; t < H2; t += 128) {
        if (t < HH) v2f[0][t] = other[((size_t)b*LL + lastIdx)*H2 + t];
        else        v2f[1][t - HH] = other[(size_t)b*LL*H2 + t];
    }
    int a0 = side == 0 ? 0 : 2, a4 = side == 0 ? 4 : 6;
    for (int t = tid; t < 4 * 4 * HH; t += 128) {
        int a = t / (4 * HH);
        int g = (t / HH) % 4;
        int h = t % HH;
        int att = (g < 2) ? (a0 + g) : (a4 + g - 2);
        v2a[a][g][h] = g_att[att][b][i0 + a][h];
    }
    __syncthreads();
    if (tid < 120) {
        int g = tid / PP, p = tid % PP;
        const int mtab[6] = {0, 1, 4, 5, 6, 7};
        const int btab[6] = {4, 25, 126, 147, 168, 189};
        int m = mtab[g], dir = g & 1, base = btab[g];
        int rowset = side * 2 + dir;
        const float4* w4 = (const float4*)(params + (m * PP + p) * HH);
        for (int a = 0; a < 4; a++) {
            const float4* v14 = (const float4*)v1s[a][dir];
            const float4* v24 = (g == 0) ? (const float4*)v2f[0]
                               : (g == 1) ? (const float4*)v2f[1]
                                          : (const float4*)v2a[a][g - 2];
            float s12 = 0.f, s22 = 0.f;
            #pragma unroll 5
            for (int c = 0; c < 25; c++) {
                float4 w = w4[c], x = v24[c], v1 = v14[c];
                float w2x = w.x*w.x, w2y = w.y*w.y, w2z = w.z*w.z, w2w = w.w*w.w;
                s12 += w2x*v1.x*x.x + w2y*v1.y*x.y + w2z*v1.z*x.z + w2w*v1.w*x.w;
                s22 += w2x*x.x*x.x + w2y*x.y*x.y + w2z*x.z*x.z + w2w*x.w*x.w;
            }
            float n1 = g_wnorm[rowset][m >> 1][b][p][i0 + a];
            float val = s12 / (fmaxf(n1, EPSF) * fmaxf(sqrtf(s22), EPSF));
            float* o = out + ((size_t)side*BB*LL + (size_t)b*LL + i0 + a)*CC;
            o[base + 1 + p] = val;
            if (p == 0) {
                float d = 0.f, q = 0.f;
                #pragma unroll 5
                for (int c = 0; c < 25; c++) {
                    float4 x = v24[c], v1 = v14[c];
                    d += v1.x*x.x + v1.y*x.y + v1.z*x.z + v1.w*x.w;
                    q += x.x*x.x + x.y*x.y + x.z*x.z + x.w*x.w;
                }
                float pn = g_norm[rowset][b][i0 + a];
                o[base] = d / (fmaxf(pn, EPSF) * fmaxf(sqrtf(q), EPSF));
            }
        }
    }
}

// ---------------- K6: fused pairwise mpm ----------------
// smem: tile 12800@0, w2s 2000@12800, anch 800@14800, invA 160@15600,
//       invT 128*21@15760, red 128*43@18448, part 160*2@23952  -> 24272 floats
__global__ void __launch_bounds__(128) k6_pairwise(const float* __restrict__ cp,
                                                   const float* __restrict__ ch,
                                                   const float* __restrict__ params,
                                                   float* __restrict__ outp)
{
    extern __shared__ float sm[];
    float* tile = sm;
    float* w2s  = sm + 12800;
    float* anch = sm + 14800;
    float* invA = sm + 15600;
    float* invT = sm + 15760;
    float* red  = sm + 18448;
    float* part = sm + 23952;

    int tid = threadIdx.x;
    int b = blockIdx.y;
    int dir = blockIdx.z;
    int ib = blockIdx.x;
    int i0 = ib * 8;
    int m = 2 + dir;

    for (int t = tid; t < PP * HH; t += 128) {
        float wv = params[m * PP * HH + t];
        w2s[t] = wv * wv;
    }
    {
        const float* abase = cp + ((size_t)b*LL + i0)*H2 + dir*HH;
        for (int t = tid; t < 8 * 25; t += 128) {
            int a = t / 25, c = t % 25;
            *(float4*)(anch + a*HH + 4*c) = *(const float4*)(abase + (size_t)a*H2 + 4*c);
        }
    }
    {
        const float* tbase = ch + (size_t)b*LL*H2 + dir*HH;
        for (int t = tid; t < 128 * 25; t += 128) {
            int j = t / 25, c = t % 25;
            *(float4*)(tile + j*HH + 4*c) = *(const float4*)(tbase + (size_t)j*H2 + 4*c);
        }
    }
    for (int t = tid; t < 8 * PP; t += 128) {
        int a = t / PP, p = t % PP;
        invA[a*PP + p] = 1.f / fmaxf(g_wnorm[dir][1][b][p][i0 + a], EPSF);
    }
    #pragma unroll
    for (int p = 0; p < PP; p++)
        invT[tid*21 + p] = 1.f / fmaxf(g_wnorm[2 + dir][1][b][p][tid], EPSF);
    __syncthreads();

    float hm[PP], hs[PP];
    #pragma unroll
    for (int p = 0; p < PP; p++) { hm[p] = -INFINITY; hs[p] = 0.f; }

    const ulonglong2* vt = (const ulonglong2*)(tile + tid*HH);
    for (int pass = 0; pass < 4; pass++) {
        int a0 = pass * 2;
        const ulonglong2* at0 = (const ulonglong2*)(anch + a0*HH);
        const ulonglong2* at1 = (const ulonglong2*)(anch + (a0+1)*HH);
        u64 acc0[PP], acc1[PP];
        #pragma unroll
        for (int p = 0; p < PP; p++) { acc0[p] = 0ull; acc1[p] = 0ull; }
        #pragma unroll 5
        for (int c = 0; c < 25; c++) {
            ulonglong2 v  = vt[c];
            ulonglong2 aa = at0[c];
            ulonglong2 bb = at1[c];
            u64 p00 = mul2(v.x, aa.x), p01 = mul2(v.y, aa.y);
            u64 p10 = mul2(v.x, bb.x), p11 = mul2(v.y, bb.y);
            #pragma unroll
            for (int p = 0; p < PP; p++) {
                ulonglong2 w = *((const ulonglong2*)(w2s + p*HH) + c);
                fma2(acc0[p], w.x, p00);
                fma2(acc0[p], w.y, p01);
                fma2(acc1[p], w.x, p10);
                fma2(acc1[p], w.y, p11);
            }
        }
        #pragma unroll
        for (int p = 0; p < PP; p++) {
            float2 x0 = up2(acc0[p]);
            float2 x1 = up2(acc1[p]);
            float it = invT[tid*21 + p];
            float v0 = (x0.x + x0.y) * invA[a0*PP + p] * it;
            float v1 = (x1.x + x1.y) * invA[(a0+1)*PP + p] * it;
            red[tid*43 + p]      = v0;
            red[tid*43 + 21 + p] = v1;
            hm[p] = fmaxf(hm[p], fmaxf(v0, v1));
            hs[p] += v0; hs[p] += v1;
        }
        __syncthreads();
        // stage1: 160 tasks over 128 threads
        for (int t = tid; t < 160; t += 128) {
            int a = t / 80, p = (t % 80) >> 2, q = t & 3;
            float mx = -INFINITY, s = 0.f;
            int base = q * 32;
            for (int k = 0; k < 32; k++) {
                float v = red[(base + k)*43 + a*21 + p];
                mx = fmaxf(mx, v); s += v;
            }
            part[t*2] = mx; part[t*2 + 1] = s;
        }
        __syncthreads();
        if (tid < 40) {
            int a = tid / PP, p = tid % PP;
            float mx = -INFINITY, s = 0.f;
            #pragma unroll
            for (int q = 0; q < 4; q++) {
                int t = a*80 + p*4 + q;
                mx = fmaxf(mx, part[t*2]);
                s += part[t*2 + 1];
            }
            float* o = outp + ((size_t)b*LL + i0 + a0 + a)*CC;
            o[46 + dir*40 + p] = mx;
            o[66 + dir*40 + p] = s * (1.f/LL);
        }
    }

    float* gp = &g_hp[dir][b][ib][tid][0];
    #pragma unroll
    for (int p = 0; p < PP; p++) {
        gp[2*p]     = hm[p];
        gp[2*p + 1] = hs[p];
    }
}

// ---------------- K7: reduce mv_h partials ----------------
__global__ void __launch_bounds__(128) k7_reduce(float* __restrict__ out)
{
    int b = blockIdx.x, dir = blockIdx.y, j = threadIdx.x;
    float* o = out + (size_t)BB*LL*CC + ((size_t)b*LL + j)*CC;
    for (int p = 0; p < PP; p++) {
        float mx = -INFINITY, s = 0.f;
        #pragma unroll
        for (int ib = 0; ib < 16; ib++) {
            float2 v = *(const float2*)&g_hp[dir][b][ib][j][2*p];
            mx = fmaxf(mx, v.x); s += v.y;
        }
        o[46 + dir*40 + p] = mx;
        o[66 + dir*40 + p] = s * (1.f/LL);
    }
}

// ---------------- launch ----------------
extern "C" void kernel_launch(void* const* d_in, const int* in_sizes, int n_in,
                              void* d_out, int out_size)
{
    const float* cp     = (const float*)d_in[0];
    const int*   mp     = (const int*)d_in[1];
    const float* ch     = (const float*)d_in[2];
    const int*   mh     = (const int*)d_in[3];
    const float* params = (const float*)d_in[4];
    float* out = (float*)d_out;
    float* out_h = out + (size_t)BB*LL*CC;

    static int attr_done = 0;
    if (!attr_done) {
        cudaFuncSetAttribute(k23_rows,    cudaFuncAttributeMaxDynamicSharedMemorySize, 131840);
        cudaFuncSetAttribute(k4_cols,     cudaFuncAttributeMaxDynamicSharedMemorySize, 119040);
        cudaFuncSetAttribute(k6_pairwise, cudaFuncAttributeMaxDynamicSharedMemorySize, 97088);
        attr_done = 1;
    }

    k0_last<<<1, 32>>>(mp, mh);
    k1_norms<<<dim3(LL/8, BB), 128>>>(cp, ch, params);
    k23_rows<<<dim3(LL/16, BB), 256, 131840>>>(cp, ch, out);
    k4_cols<<<dim3(LL/16, BB), 256, 119040>>>(cp, out_h);
    k5_vec<<<dim3(LL/4, BB, 2), 128>>>(cp, ch, params, out);
    k6_pairwise<<<dim3(LL/8, BB, 2), 128, 97088>>>(cp, ch, params, out);
    k7_reduce<<<dim3(BB, 2), 128>>>(out);
}

// round 4
// speedup vs baseline: 2.0295x; 1.0050x over previous
#include <cuda_runtime.h>
#include <math.h>

#define BB 16
#define LL 128
#define HH 100
#define H2 200
#define PP 20
#define CC 210
#define EPSF 1e-8f

typedef unsigned long long u64;

__device__ __forceinline__ u64 mul2(u64 a, u64 b) {
    u64 d; asm("mul.rn.f32x2 %0,%1,%2;" : "=l"(d) : "l"(a), "l"(b)); return d;
}
__device__ __forceinline__ void fma2(u64& d, u64 a, u64 b) {
    asm("fma.rn.f32x2 %0,%1,%2,%0;" : "+l"(d) : "l"(a), "l"(b));
}
__device__ __forceinline__ float2 up2(u64 x) {
    float2 r; asm("mov.b64 {%0,%1}, %2;" : "=f"(r.x), "=f"(r.y) : "l"(x)); return r;
}

// ---------------- scratch ----------------
__device__ float g_norm[4][BB][LL];
__device__ float g_wnorm[4][4][BB][PP][LL];
__device__ __align__(16) float g_att[8][BB][LL][HH];
__device__ __align__(16) float g_cos[2][BB][LL][LL];   // [dir][b][i][j]
__device__ int   g_last[2][BB];
__device__ __align__(16) float g_hp[2][BB][16][LL][2*PP];

// ---------------- K0 ----------------
__global__ void k0_last(const int* __restrict__ mp, const int* __restrict__ mh)
{
    int b = threadIdx.x;
    if (b < BB) {
        int lp = 0, lh = 0;
        for (int j = 0; j < LL; j++) { lp += mp[b*LL + j]; lh += mh[b*LL + j]; }
        g_last[0][b] = max(lp - 1, 0);
        g_last[1][b] = max(lh - 1, 0);
    }
}

// ---------------- K1: norms ----------------
__global__ void __launch_bounds__(128) k1_norms(const float* __restrict__ cp,
                                                const float* __restrict__ ch,
                                                const float* __restrict__ params)
{
    int b = blockIdx.y, i0 = blockIdx.x * 8, tid = threadIdx.x;
    __shared__ float vsq[8][4][HH];
    for (int t = tid; t < 8 * 2 * H2; t += 128) {
        int a = t / (2 * H2);
        int rem = t % (2 * H2);
        float v;
        if (rem < H2) v = cp[((size_t)b*LL + i0 + a)*H2 + rem];
        else          v = ch[((size_t)b*LL + i0 + a)*H2 + rem - H2];
        vsq[a][rem / HH][rem % HH] = v * v;
    }
    __syncthreads();
    if (tid < 32) {
        int a = tid >> 2, r = tid & 3;
        float s = 0.f;
        for (int h = 0; h < HH; h++) s += vsq[a][r][h];
        g_norm[r][b][i0 + a] = sqrtf(s);
    }
    for (int t = tid; t < 4 * 4 * PP; t += 128) {
        int r = t / (4 * PP);
        int rem = t % (4 * PP);
        int ml = rem / PP, p = rem % PP;
        int m = (r & 1) ? (2 * ml + 1) : (2 * ml);
        const float* w = params + (m * PP + p) * HH;
        float s[8] = {0,0,0,0,0,0,0,0};
        for (int h = 0; h < HH; h++) {
            float wv = w[h]; float w2 = wv * wv;
            #pragma unroll
            for (int a = 0; a < 8; a++) s[a] += w2 * vsq[a][r][h];
        }
        #pragma unroll
        for (int a = 0; a < 8; a++) g_wnorm[r][ml][b][p][i0 + a] = sqrtf(s[a]);
    }
}

// ---------------- K23: cos + row stats + attentive h vectors (8 anchors/block) ----
__global__ void __launch_bounds__(256) k23_rows(const float* __restrict__ cp,
                                                const float* __restrict__ ch,
                                                float* __restrict__ outp)
{
    __shared__ __align__(16) float pan[8 * H2];
    __shared__ float cosr[2 * 8 * LL];
    __shared__ float stat[2 * 8 * 2];

    int b = blockIdx.y, i0 = blockIdx.x * 8, tid = threadIdx.x;

    const float4* psrc = (const float4*)(cp + ((size_t)b*LL + i0)*H2);
    float4* pdst = (float4*)pan;
    for (int t = tid; t < 8 * 50; t += 256) pdst[t] = psrc[t];
    __syncthreads();

    int dir = tid >> 7, j = tid & 127;
    {
        const float4* tr = (const float4*)(ch + ((size_t)b*LL + j)*H2 + dir*HH);
        float nj = g_norm[2 + dir][b][j];
        float dacc[8];
        #pragma unroll
        for (int a = 0; a < 8; a++) dacc[a] = 0.f;
        const float4* pb = (const float4*)(pan + dir*HH);
        #pragma unroll 5
        for (int c = 0; c < 25; c++) {
            float4 v = tr[c];
            #pragma unroll
            for (int a = 0; a < 8; a++) {
                float4 w = pb[a*50 + c];
                dacc[a] += v.x*w.x + v.y*w.y + v.z*w.z + v.w*w.w;
            }
        }
        #pragma unroll
        for (int a = 0; a < 8; a++) {
            float ni = g_norm[dir][b][i0 + a];
            float cv = dacc[a] / fmaxf(ni * nj, EPSF);
            cosr[(dir*8 + a)*128 + j] = cv;
            g_cos[dir][b][i0 + a][j] = cv;
        }
    }
    __syncthreads();

    int w = tid >> 5, lane = tid & 31;
    for (int task = w; task < 16; task += 8) {
        int d = task >> 3, a = task & 7;
        float mx = -INFINITY, s = 0.f;
        for (int jj = lane; jj < 128; jj += 32) {
            float v = cosr[(d*8 + a)*128 + jj];
            mx = fmaxf(mx, v); s += v;
        }
        #pragma unroll
        for (int o = 16; o; o >>= 1) {
            mx = fmaxf(mx, __shfl_xor_sync(0xffffffffu, mx, o));
            s += __shfl_xor_sync(0xffffffffu, s, o);
        }
        if (lane == 0) { stat[(d*8 + a)*2] = mx; stat[(d*8 + a)*2 + 1] = s; }
    }
    __syncthreads();

    if (tid < 8) {
        float* o = outp + ((size_t)b*LL + i0 + tid)*CC;
        o[0] = stat[tid*2];         o[1] = stat[tid*2 + 1] * (1.f/LL);
        o[2] = stat[(8+tid)*2];     o[3] = stat[(8+tid)*2 + 1] * (1.f/LL);
    }

    if (tid < 200) {
        int d = tid >= 100;
        float inv[8], smv[8], mxv[8];
        #pragma unroll
        for (int a = 0; a < 8; a++) {
            inv[a] = 1.f / fmaxf(stat[(d*8 + a)*2 + 1], EPSF);
            smv[a] = 0.f; mxv[a] = -INFINITY;
        }
        const float* crow = cosr + d*8*128;
        const float* gb = ch + (size_t)b*LL*H2 + tid;
        for (int jj = 0; jj < 128; jj += 2) {
            float hv0 = gb[(size_t)jj*H2];
            float hv1 = gb[(size_t)(jj+1)*H2];
            #pragma unroll
            for (int a = 0; a < 8; a++) {
                float2 c2 = *(const float2*)&crow[a*128 + jj];
                float v0 = c2.x * hv0, v1 = c2.y * hv1;
                smv[a] += v0; smv[a] += v1;
                mxv[a] = fmaxf(mxv[a], fmaxf(v0, v1));
            }
        }
        int h = d ? tid - 100 : tid;
        for (int a = 0; a < 8; a++) {
            g_att[d ? 1 : 0][b][i0 + a][h] = smv[a] * inv[a];
            g_att[d ? 5 : 4][b][i0 + a][h] = mxv[a];
        }
    }
}

// ---------------- K4: col stats + attentive p vectors (8 j-anchors/block) ----
__global__ void __launch_bounds__(256) k4_cols(const float* __restrict__ cp,
                                               float* __restrict__ outh)
{
    __shared__ float cosc[2 * 8 * LL];
    __shared__ float stat[2 * 8 * 2];

    int b = blockIdx.y, j0 = blockIdx.x * 8, tid = threadIdx.x;

    for (int t = tid; t < 2 * 128 * 2; t += 256) {
        int d = t >> 8, rem = t & 255, i = rem >> 1, q = rem & 1;
        float4 v = *(const float4*)&g_cos[d][b][i][j0 + q*4];
        cosc[(d*8 + q*4 + 0)*128 + i] = v.x;
        cosc[(d*8 + q*4 + 1)*128 + i] = v.y;
        cosc[(d*8 + q*4 + 2)*128 + i] = v.z;
        cosc[(d*8 + q*4 + 3)*128 + i] = v.w;
    }
    __syncthreads();

    int w = tid >> 5, lane = tid & 31;
    for (int task = w; task < 16; task += 8) {
        int idx = task * 128;
        float mx = -INFINITY, s = 0.f;
        for (int ii = lane; ii < 128; ii += 32) {
            float v = cosc[idx + ii];
            mx = fmaxf(mx, v); s += v;
        }
        #pragma unroll
        for (int o = 16; o; o >>= 1) {
            mx = fmaxf(mx, __shfl_xor_sync(0xffffffffu, mx, o));
            s += __shfl_xor_sync(0xffffffffu, s, o);
        }
        if (lane == 0) { stat[task*2] = mx; stat[task*2 + 1] = s; }
    }
    __syncthreads();

    if (tid < 8) {
        float* o = outh + ((size_t)b*LL + j0 + tid)*CC;
        o[0] = stat[tid*2];         o[1] = stat[tid*2 + 1] * (1.f/LL);
        o[2] = stat[(8+tid)*2];     o[3] = stat[(8+tid)*2 + 1] * (1.f/LL);
    }

    if (tid < 200) {
        int d = tid >= 100;
        float inv[8], smv[8], mxv[8];
        #pragma unroll
        for (int a = 0; a < 8; a++) {
            inv[a] = 1.f / fmaxf(stat[(d*8 + a)*2 + 1], EPSF);
            smv[a] = 0.f; mxv[a] = -INFINITY;
        }
        const float* crow = cosc + d*8*128;
        const float* gb = cp + (size_t)b*LL*H2 + tid;
        for (int ii = 0; ii < 128; ii += 2) {
            float pv0 = gb[(size_t)ii*H2];
            float pv1 = gb[(size_t)(ii+1)*H2];
            #pragma unroll
            for (int a = 0; a < 8; a++) {
                float2 c2 = *(const float2*)&crow[a*128 + ii];
                float v0 = c2.x * pv0, v1 = c2.y * pv1;
                smv[a] += v0; smv[a] += v1;
                mxv[a] = fmaxf(mxv[a], fmaxf(v0, v1));
            }
        }
        int h = d ? tid - 100 : tid;
        for (int a = 0; a < 8; a++) {
            g_att[d ? 3 : 2][b][j0 + a][h] = smv[a] * inv[a];
            g_att[d ? 7 : 6][b][j0 + a][h] = mxv[a];
        }
    }
}

// ---------------- K5: vector-mpm groups ----------------
__global__ void __launch_bounds__(128) k5_vec(const float* __restrict__ cp,
                                              const float* __restrict__ ch,
                                              const float* __restrict__ params,
                                              float* __restrict__ out)
{
    int b = blockIdx.y, side = blockIdx.z, i0 = blockIdx.x * 4, tid = threadIdx.x;
    __shared__ __align__(16) float v1s[4][2][HH];
    __shared__ __align__(16) float v2f[2][HH];
    __shared__ __align__(16) float v2a[4][4][HH];
    const float* base1 = side == 0 ? cp : ch;
    const float* other = side == 0 ? ch : cp;
    for (int t = tid; t < 4 * H2; t += 128) {
        int a = t / H2, rem = t % H2;
        v1s[a][rem / HH][rem % HH] = base1[((size_t)b*LL + i0 + a)*H2 + rem];
    }
    int lastIdx = g_last[side == 0 ? 1 : 0][b];
    for (int t = tid; t < H2; t += 128) {
        if (t < HH) v2f[0][t] = other[((size_t)b*LL + lastIdx)*H2 + t];
        else        v2f[1][t - HH] = other[(size_t)b*LL*H2 + t];
    }
    int a0 = side == 0 ? 0 : 2, a4 = side == 0 ? 4 : 6;
    for (int t = tid; t < 4 * 4 * HH; t += 128) {
        int a = t / (4 * HH);
        int g = (t / HH) % 4;
        int h = t % HH;
        int att = (g < 2) ? (a0 + g) : (a4 + g - 2);
        v2a[a][g][h] = g_att[att][b][i0 + a][h];
    }
    __syncthreads();
    if (tid < 120) {
        int g = tid / PP, p = tid % PP;
        const int mtab[6] = {0, 1, 4, 5, 6, 7};
        const int btab[6] = {4, 25, 126, 147, 168, 189};
        int m = mtab[g], dir = g & 1, base = btab[g];
        int rowset = side * 2 + dir;
        const float4* w4 = (const float4*)(params + (m * PP + p) * HH);
        for (int a = 0; a < 4; a++) {
            const float4* v14 = (const float4*)v1s[a][dir];
            const float4* v24 = (g == 0) ? (const float4*)v2f[0]
                               : (g == 1) ? (const float4*)v2f[1]
                                          : (const float4*)v2a[a][g - 2];
            float s12 = 0.f, s22 = 0.f;
            #pragma unroll 5
            for (int c = 0; c < 25; c++) {
                float4 w = w4[c], x = v24[c], v1 = v14[c];
                float w2x = w.x*w.x, w2y = w.y*w.y, w2z = w.z*w.z, w2w = w.w*w.w;
                s12 += w2x*v1.x*x.x + w2y*v1.y*x.y + w2z*v1.z*x.z + w2w*v1.w*x.w;
                s22 += w2x*x.x*x.x + w2y*x.y*x.y + w2z*x.z*x.z + w2w*x.w*x.w;
            }
            float n1 = g_wnorm[rowset][m >> 1][b][p][i0 + a];
            float val = s12 / (fmaxf(n1, EPSF) * fmaxf(sqrtf(s22), EPSF));
            float* o = out + ((size_t)side*BB*LL + (size_t)b*LL + i0 + a)*CC;
            o[base + 1 + p] = val;
            if (p == 0) {
                float d = 0.f, q = 0.f;
                #pragma unroll 5
                for (int c = 0; c < 25; c++) {
                    float4 x = v24[c], v1 = v14[c];
                    d += v1.x*x.x + v1.y*x.y + v1.z*x.z + v1.w*x.w;
                    q += x.x*x.x + x.y*x.y + x.z*x.z + x.w*x.w;
                }
                float pn = g_norm[rowset][b][i0 + a];
                o[base] = d / (fmaxf(pn, EPSF) * fmaxf(sqrtf(q), EPSF));
            }
        }
    }
}

// ---------------- K6: fused pairwise mpm ----------------
__global__ void __launch_bounds__(128) k6_pairwise(const float* __restrict__ cp,
                                                   const float* __restrict__ ch,
                                                   const float* __restrict__ params,
                                                   float* __restrict__ outp)
{
    extern __shared__ float sm[];
    float* tile = sm;
    float* w2s  = sm + 12800;
    float* anch = sm + 14800;
    float* invA = sm + 15600;
    float* invT = sm + 15760;
    float* red  = sm + 18448;
    float* part = sm + 23952;

    int tid = threadIdx.x;
    int b = blockIdx.y;
    int dir = blockIdx.z;
    int ib = blockIdx.x;
    int i0 = ib * 8;
    int m = 2 + dir;

    for (int t = tid; t < PP * HH; t += 128) {
        float wv = params[m * PP * HH + t];
        w2s[t] = wv * wv;
    }
    {
        const float* abase = cp + ((size_t)b*LL + i0)*H2 + dir*HH;
        for (int t = tid; t < 8 * 25; t += 128) {
            int a = t / 25, c = t % 25;
            *(float4*)(anch + a*HH + 4*c) = *(const float4*)(abase + (size_t)a*H2 + 4*c);
        }
    }
    {
        const float* tbase = ch + (size_t)b*LL*H2 + dir*HH;
        for (int t = tid; t < 128 * 25; t += 128) {
            int j = t / 25, c = t % 25;
            *(float4*)(tile + j*HH + 4*c) = *(const float4*)(tbase + (size_t)j*H2 + 4*c);
        }
    }
    for (int t = tid; t < 8 * PP; t += 128) {
        int a = t / PP, p = t % PP;
        invA[a*PP + p] = 1.f / fmaxf(g_wnorm[dir][1][b][p][i0 + a], EPSF);
    }
    #pragma unroll
    for (int p = 0; p < PP; p++)
        invT[tid*21 + p] = 1.f / fmaxf(g_wnorm[2 + dir][1][b][p][tid], EPSF);
    __syncthreads();

    float hm[PP], hs[PP];
    #pragma unroll
    for (int p = 0; p < PP; p++) { hm[p] = -INFINITY; hs[p] = 0.f; }

    const ulonglong2* vt = (const ulonglong2*)(tile + tid*HH);
    for (int pass = 0; pass < 4; pass++) {
        int a0 = pass * 2;
        const ulonglong2* at0 = (const ulonglong2*)(anch + a0*HH);
        const ulonglong2* at1 = (const ulonglong2*)(anch + (a0+1)*HH);
        u64 acc0[PP], acc1[PP];
        #pragma unroll
        for (int p = 0; p < PP; p++) { acc0[p] = 0ull; acc1[p] = 0ull; }
        #pragma unroll 5
        for (int c = 0; c < 25; c++) {
            ulonglong2 v  = vt[c];
            ulonglong2 aa = at0[c];
            ulonglong2 bb = at1[c];
            u64 p00 = mul2(v.x, aa.x), p01 = mul2(v.y, aa.y);
            u64 p10 = mul2(v.x, bb.x), p11 = mul2(v.y, bb.y);
            #pragma unroll
            for (int p = 0; p < PP; p++) {
                ulonglong2 w = *((const ulonglong2*)(w2s + p*HH) + c);
                fma2(acc0[p], w.x, p00);
                fma2(acc0[p], w.y, p01);
                fma2(acc1[p], w.x, p10);
                fma2(acc1[p], w.y, p11);
            }
        }
        #pragma unroll
        for (int p = 0; p < PP; p++) {
            float2 x0 = up2(acc0[p]);
            float2 x1 = up2(acc1[p]);
            float it = invT[tid*21 + p];
            float v0 = (x0.x + x0.y) * invA[a0*PP + p] * it;
            float v1 = (x1.x + x1.y) * invA[(a0+1)*PP + p] * it;
            red[tid*43 + p]      = v0;
            red[tid*43 + 21 + p] = v1;
            hm[p] = fmaxf(hm[p], fmaxf(v0, v1));
            hs[p] += v0; hs[p] += v1;
        }
        __syncthreads();
        for (int t = tid; t < 160; t += 128) {
            int a = t / 80, p = (t % 80) >> 2, q = t & 3;
            float mx = -INFINITY, s = 0.f;
            int base = q * 32;
            for (int k = 0; k < 32; k++) {
                float v = red[(base + k)*43 + a*21 + p];
                mx = fmaxf(mx, v); s += v;
            }
            part[t*2] = mx; part[t*2 + 1] = s;
        }
        __syncthreads();
        if (tid < 40) {
            int a = tid / PP, p = tid % PP;
            float mx = -INFINITY, s = 0.f;
            #pragma unroll
            for (int q = 0; q < 4; q++) {
                int t = a*80 + p*4 + q;
                mx = fmaxf(mx, part[t*2]);
                s += part[t*2 + 1];
            }
            float* o = outp + ((size_t)b*LL + i0 + a0 + a)*CC;
            o[46 + dir*40 + p] = mx;
            o[66 + dir*40 + p] = s * (1.f/LL);
        }
    }

    float* gp = &g_hp[dir][b][ib][tid][0];
    #pragma unroll
    for (int p = 0; p < PP; p++) {
        gp[2*p]     = hm[p];
        gp[2*p + 1] = hs[p];
    }
}

// ---------------- K7: reduce mv_h partials ----------------
__global__ void __launch_bounds__(128) k7_reduce(float* __restrict__ out)
{
    int b = blockIdx.x, dir = blockIdx.y, j = threadIdx.x;
    float* o = out + (size_t)BB*LL*CC + ((size_t)b*LL + j)*CC;
    for (int p = 0; p < PP; p++) {
        float mx = -INFINITY, s = 0.f;
        #pragma unroll
        for (int ib = 0; ib < 16; ib++) {
            float2 v = *(const float2*)&g_hp[dir][b][ib][j][2*p];
            mx = fmaxf(mx, v.x); s += v.y;
        }
        o[46 + dir*40 + p] = mx;
        o[66 + dir*40 + p] = s * (1.f/LL);
    }
}

// ---------------- launch ----------------
extern "C" void kernel_launch(void* const* d_in, const int* in_sizes, int n_in,
                              void* d_out, int out_size)
{
    const float* cp     = (const float*)d_in[0];
    const int*   mp     = (const int*)d_in[1];
    const float* ch     = (const float*)d_in[2];
    const int*   mh     = (const int*)d_in[3];
    const float* params = (const float*)d_in[4];
    float* out = (float*)d_out;
    float* out_h = out + (size_t)BB*LL*CC;

    static int attr_done = 0;
    if (!attr_done) {
        cudaFuncSetAttribute(k6_pairwise, cudaFuncAttributeMaxDynamicSharedMemorySize, 97088);
        attr_done = 1;
    }

    k0_last<<<1, 32>>>(mp, mh);
    k1_norms<<<dim3(LL/8, BB), 128>>>(cp, ch, params);
    k23_rows<<<dim3(LL/8, BB), 256>>>(cp, ch, out);
    k4_cols<<<dim3(LL/8, BB), 256>>>(cp, out_h);
    k5_vec<<<dim3(LL/4, BB, 2), 128>>>(cp, ch, params, out);
    k6_pairwise<<<dim3(LL/8, BB, 2), 128, 97088>>>(cp, ch, params, out);
    k7_reduce<<<dim3(BB, 2), 128>>>(out);
}